// round 1
// baseline (speedup 1.0000x reference)
#include <cuda_runtime.h>
#include <cstdint>
#include <cstdio>

#define CC 128
#define HH 256
#define LL 4
#define NMAX 50176
#define EMAX 602112

// ---------------- scratch (device globals; no allocation allowed) ------------
__device__ float  g_x [NMAX * CC];   // running node features (residual stream)
__device__ float  g_h [NMAX * CC];   // post GraphNorm + ReLU
__device__ float  g_o [NMAX * CC];   // GENConv aggregation output (pre-MLP)
__device__ float  g_h1[NMAX * HH];   // MLP hidden (pre-LN)
__device__ int    g_rowptr[NMAX + 1];
__device__ int    g_cursor[NMAX];
__device__ int    g_col[EMAX];       // src ids grouped by dst (CSR)
__device__ float  g_gnsum[CC];
__device__ float  g_gnsq [CC];
__device__ double g_lnsum;
__device__ double g_lnsq;

// ---------------- small utility kernels --------------------------------------
__global__ void k_copyin(const float* __restrict__ x, int n4)
{
    int i = blockIdx.x * blockDim.x + threadIdx.x;
    int stride = gridDim.x * blockDim.x;
    const float4* src = (const float4*)x;
    float4* dst = (float4*)g_x;
    for (; i < n4; i += stride) dst[i] = src[i];
}

__global__ void k_zero_cursor(int n)
{
    int i = blockIdx.x * blockDim.x + threadIdx.x;
    if (i < n) g_cursor[i] = 0;
}

__global__ void k_count(const int* __restrict__ dst, int E)
{
    int i = blockIdx.x * blockDim.x + threadIdx.x;
    int stride = gridDim.x * blockDim.x;
    for (; i < E; i += stride) atomicAdd(&g_cursor[dst[i]], 1);
}

__global__ void k_scan(int n)
{
    __shared__ int sh[1024];
    __shared__ int carry;
    if (threadIdx.x == 0) carry = 0;
    __syncthreads();
    for (int base = 0; base < n; base += 1024) {
        int i = base + threadIdx.x;
        int v = (i < n) ? g_cursor[i] : 0;
        sh[threadIdx.x] = v;
        __syncthreads();
        for (int off = 1; off < 1024; off <<= 1) {
            int tv = (threadIdx.x >= off) ? sh[threadIdx.x - off] : 0;
            __syncthreads();
            sh[threadIdx.x] += tv;
            __syncthreads();
        }
        int excl = sh[threadIdx.x] - v + carry;
        if (i < n) { g_rowptr[i] = excl; g_cursor[i] = excl; }
        __syncthreads();
        if (threadIdx.x == 0) carry += sh[1023];
        __syncthreads();
    }
    if (threadIdx.x == 0) g_rowptr[n] = carry;
}

__global__ void k_fill(const int* __restrict__ src, const int* __restrict__ dst, int E)
{
    int i = blockIdx.x * blockDim.x + threadIdx.x;
    int stride = gridDim.x * blockDim.x;
    for (; i < E; i += stride) {
        int p = atomicAdd(&g_cursor[dst[i]], 1);
        g_col[p] = src[i];
    }
}

__global__ void k_zero_stats()
{
    int i = threadIdx.x;
    g_gnsum[i] = 0.f;
    g_gnsq[i]  = 0.f;
    if (i == 0) { g_lnsum = 0.0; g_lnsq = 0.0; }
}

// ---------------- GraphNorm ---------------------------------------------------
__global__ void k_gn_reduce(int n)
{
    int c = threadIdx.x;  // 128 threads
    float s = 0.f, q = 0.f;
    for (int row = blockIdx.x; row < n; row += gridDim.x) {
        float v = g_x[(size_t)row * CC + c];
        s += v;
        q += v * v;
    }
    atomicAdd(&g_gnsum[c], s);
    atomicAdd(&g_gnsq[c],  q);
}

__global__ void k_gn_apply(int n, const float* __restrict__ gnw,
                           const float* __restrict__ gnb, const float* __restrict__ gna)
{
    int c = threadIdx.x;
    float invn  = 1.f / (float)n;
    float mean  = g_gnsum[c] * invn;
    float a     = gna[c];
    float var   = g_gnsq[c] * invn - (2.f * a - a * a) * mean * mean;
    float winv  = gnw[c] * rsqrtf(var + 1e-5f);
    float am    = a * mean;
    float b     = gnb[c];
    for (int row = blockIdx.x; row < n; row += gridDim.x) {
        float v = g_x[(size_t)row * CC + c];
        float y = winv * (v - am) + b;
        g_h[(size_t)row * CC + c] = fmaxf(y, 0.f);
    }
}

// ---------------- GENConv softmax aggregation (warp per node, no atomics) -----
__global__ void k_edge(int n, const float* __restrict__ t_ptr)
{
    int warp = (blockIdx.x * blockDim.x + threadIdx.x) >> 5;
    if (warp >= n) return;
    int lane = threadIdx.x & 31;
    float t = __ldg(t_ptr);
    int beg = g_rowptr[warp], end = g_rowptr[warp + 1];
    int co = lane * 4;

    float4 mx = make_float4(-3.4e38f, -3.4e38f, -3.4e38f, -3.4e38f);
    for (int e = beg; e < end; e++) {
        int s = g_col[e];
        float4 v = *(const float4*)(g_h + (size_t)s * CC + co);
        mx.x = fmaxf(mx.x, t * (fmaxf(v.x, 0.f) + 1e-7f));
        mx.y = fmaxf(mx.y, t * (fmaxf(v.y, 0.f) + 1e-7f));
        mx.z = fmaxf(mx.z, t * (fmaxf(v.z, 0.f) + 1e-7f));
        mx.w = fmaxf(mx.w, t * (fmaxf(v.w, 0.f) + 1e-7f));
    }
    float4 s1 = make_float4(0.f, 0.f, 0.f, 0.f);
    float4 s2 = make_float4(0.f, 0.f, 0.f, 0.f);
    for (int e = beg; e < end; e++) {
        int s = g_col[e];
        float4 v = *(const float4*)(g_h + (size_t)s * CC + co);
        float mX = fmaxf(v.x, 0.f) + 1e-7f;
        float mY = fmaxf(v.y, 0.f) + 1e-7f;
        float mZ = fmaxf(v.z, 0.f) + 1e-7f;
        float mW = fmaxf(v.w, 0.f) + 1e-7f;
        float eX = __expf(t * mX - mx.x);
        float eY = __expf(t * mY - mx.y);
        float eZ = __expf(t * mZ - mx.z);
        float eW = __expf(t * mW - mx.w);
        s1.x += eX; s1.y += eY; s1.z += eZ; s1.w += eW;
        s2.x += mX * eX; s2.y += mY * eY; s2.z += mZ * eZ; s2.w += mW * eW;
    }
    float4 hn = *(const float4*)(g_h + (size_t)warp * CC + co);
    float4 o;
    o.x = s2.x / (s1.x + 1e-16f) + hn.x;
    o.y = s2.y / (s1.y + 1e-16f) + hn.y;
    o.z = s2.z / (s1.z + 1e-16f) + hn.z;
    o.w = s2.w / (s1.w + 1e-16f) + hn.w;
    *(float4*)(g_o + (size_t)warp * CC + co) = o;
}

// ---------------- GEMM1: h1 = o @ W1 + b1, fused scalar-LN stats -------------
__global__ __launch_bounds__(256, 2)
void k_gemm1(int M, const float* __restrict__ W1l, const float* __restrict__ b1l)
{
    __shared__ float sA[16][129];
    __shared__ float sB[16][128];
    int tid = threadIdx.x;
    int tx = tid & 15, ty = tid >> 4;
    int rowBase = blockIdx.x * 128;
    int colBase = blockIdx.y * 128;
    float acc[8][8];
#pragma unroll
    for (int i = 0; i < 8; i++)
#pragma unroll
        for (int j = 0; j < 8; j++) acc[i][j] = 0.f;

    int ar  = tid >> 2;
    int akc = (tid & 3) * 4;
    int br  = tid >> 5;
    int bc  = (tid & 31) * 4;

    for (int k0 = 0; k0 < CC; k0 += 16) {
#pragma unroll
        for (int p = 0; p < 2; p++) {
            int r = ar + p * 64;
            int grow = rowBase + r;
            float4 v = make_float4(0.f, 0.f, 0.f, 0.f);
            if (grow < M) v = *(const float4*)(g_o + (size_t)grow * CC + k0 + akc);
            sA[akc + 0][r] = v.x; sA[akc + 1][r] = v.y;
            sA[akc + 2][r] = v.z; sA[akc + 3][r] = v.w;
        }
#pragma unroll
        for (int p = 0; p < 2; p++) {
            int r = br + p * 8;
            float4 v = *(const float4*)(W1l + (size_t)(k0 + r) * HH + colBase + bc);
            *(float4*)&sB[r][bc] = v;
        }
        __syncthreads();
#pragma unroll
        for (int kk = 0; kk < 16; kk++) {
            float a_[8], b_[8];
#pragma unroll
            for (int i = 0; i < 8; i++) a_[i] = sA[kk][ty * 8 + i];
#pragma unroll
            for (int j = 0; j < 8; j++) b_[j] = sB[kk][tx * 8 + j];
#pragma unroll
            for (int i = 0; i < 8; i++)
#pragma unroll
                for (int j = 0; j < 8; j++)
                    acc[i][j] = fmaf(a_[i], b_[j], acc[i][j]);
        }
        __syncthreads();
    }

    float lsum = 0.f, lsq = 0.f;
#pragma unroll
    for (int i = 0; i < 8; i++) {
        int r = rowBase + ty * 8 + i;
        if (r >= M) continue;
#pragma unroll
        for (int j = 0; j < 8; j += 4) {
            int cc = colBase + tx * 8 + j;
            float4 b4 = *(const float4*)(b1l + cc);
            float4 v = make_float4(acc[i][j] + b4.x, acc[i][j + 1] + b4.y,
                                   acc[i][j + 2] + b4.z, acc[i][j + 3] + b4.w);
            *(float4*)(g_h1 + (size_t)r * HH + cc) = v;
            lsum += (v.x + v.y) + (v.z + v.w);
            lsq  += v.x * v.x + v.y * v.y + v.z * v.z + v.w * v.w;
        }
    }
    for (int off = 16; off; off >>= 1) {
        lsum += __shfl_down_sync(0xFFFFFFFFu, lsum, off);
        lsq  += __shfl_down_sync(0xFFFFFFFFu, lsq,  off);
    }
    __shared__ float rs[8], rq[8];
    int wid = tid >> 5, lane = tid & 31;
    if (lane == 0) { rs[wid] = lsum; rq[wid] = lsq; }
    __syncthreads();
    if (tid == 0) {
        float s = 0.f, q = 0.f;
        for (int w = 0; w < 8; w++) { s += rs[w]; q += rq[w]; }
        atomicAdd(&g_lnsum, (double)s);
        atomicAdd(&g_lnsq,  (double)q);
    }
}

// ---------------- GEMM2: x += relu(LN(h1)*lnw+lnb) @ W2 + b2 -----------------
__global__ __launch_bounds__(256, 2)
void k_gemm2(int M, const float* __restrict__ W2l, const float* __restrict__ b2l,
             const float* __restrict__ lnw, const float* __restrict__ lnb)
{
    __shared__ float sA[16][129];
    __shared__ float sB[16][128];
    int tid = threadIdx.x;
    int tx = tid & 15, ty = tid >> 4;
    int rowBase = blockIdx.x * 128;

    double cnt = (double)M * (double)HH;
    double dm  = g_lnsum / cnt;
    double dv  = g_lnsq / cnt - dm * dm;
    float mean = (float)dm;
    float stdv = sqrtf(fmaxf((float)dv, 0.f));
    float inv  = 1.f / (stdv + 1e-5f);

    float acc[8][8];
#pragma unroll
    for (int i = 0; i < 8; i++)
#pragma unroll
        for (int j = 0; j < 8; j++) acc[i][j] = 0.f;

    int ar  = tid >> 2;
    int akc = (tid & 3) * 4;
    int br  = tid >> 5;
    int bc  = (tid & 31) * 4;

    for (int k0 = 0; k0 < HH; k0 += 16) {
#pragma unroll
        for (int p = 0; p < 2; p++) {
            int r = ar + p * 64;
            int grow = rowBase + r;
            float4 v = make_float4(0.f, 0.f, 0.f, 0.f);
            if (grow < M) v = *(const float4*)(g_h1 + (size_t)grow * HH + k0 + akc);
            float4 w4 = *(const float4*)(lnw + k0 + akc);
            float4 b4 = *(const float4*)(lnb + k0 + akc);
            v.x = fmaxf((v.x - mean) * inv * w4.x + b4.x, 0.f);
            v.y = fmaxf((v.y - mean) * inv * w4.y + b4.y, 0.f);
            v.z = fmaxf((v.z - mean) * inv * w4.z + b4.z, 0.f);
            v.w = fmaxf((v.w - mean) * inv * w4.w + b4.w, 0.f);
            sA[akc + 0][r] = v.x; sA[akc + 1][r] = v.y;
            sA[akc + 2][r] = v.z; sA[akc + 3][r] = v.w;
        }
#pragma unroll
        for (int p = 0; p < 2; p++) {
            int r = br + p * 8;
            float4 v = *(const float4*)(W2l + (size_t)(k0 + r) * CC + bc);
            *(float4*)&sB[r][bc] = v;
        }
        __syncthreads();
#pragma unroll
        for (int kk = 0; kk < 16; kk++) {
            float a_[8], b_[8];
#pragma unroll
            for (int i = 0; i < 8; i++) a_[i] = sA[kk][ty * 8 + i];
#pragma unroll
            for (int j = 0; j < 8; j++) b_[j] = sB[kk][tx * 8 + j];
#pragma unroll
            for (int i = 0; i < 8; i++)
#pragma unroll
                for (int j = 0; j < 8; j++)
                    acc[i][j] = fmaf(a_[i], b_[j], acc[i][j]);
        }
        __syncthreads();
    }

#pragma unroll
    for (int i = 0; i < 8; i++) {
        int r = rowBase + ty * 8 + i;
        if (r >= M) continue;
#pragma unroll
        for (int j = 0; j < 8; j += 4) {
            int cc = tx * 8 + j;
            float4 b4  = *(const float4*)(b2l + cc);
            float4 old = *(float4*)(g_x + (size_t)r * CC + cc);
            float4 v = make_float4(old.x + acc[i][j]     + b4.x,
                                   old.y + acc[i][j + 1] + b4.y,
                                   old.z + acc[i][j + 2] + b4.z,
                                   old.w + acc[i][j + 3] + b4.w);
            *(float4*)(g_x + (size_t)r * CC + cc) = v;
        }
    }
}

// ---------------- final projection x @ lin_w + lin_b -------------------------
__global__ void k_final(int n, const float* __restrict__ linw,
                        const float* __restrict__ linb, float* __restrict__ out)
{
    int row = (blockIdx.x * blockDim.x + threadIdx.x) >> 5;
    if (row >= n) return;
    int lane = threadIdx.x & 31;
    float4 x4 = *(const float4*)(g_x + (size_t)row * CC + lane * 4);
    float4 w4 = *(const float4*)(linw + lane * 4);
    float s = x4.x * w4.x + x4.y * w4.y + x4.z * w4.z + x4.w * w4.w;
    for (int off = 16; off; off >>= 1) s += __shfl_down_sync(0xFFFFFFFFu, s, off);
    if (lane == 0) out[row] = s + __ldg(linb);
}

// ---------------- launch ------------------------------------------------------
extern "C" void kernel_launch(void* const* d_in, const int* in_sizes, int n_in,
                              void* d_out, int out_size)
{
    const float* x    = (const float*)d_in[0];
    const int*   src  = (const int*)  d_in[1];
    const int*   dst  = (const int*)  d_in[2];
    const float* W1   = (const float*)d_in[3];
    const float* b1   = (const float*)d_in[4];
    const float* lnw  = (const float*)d_in[5];
    const float* lnb  = (const float*)d_in[6];
    const float* W2   = (const float*)d_in[7];
    const float* b2   = (const float*)d_in[8];
    const float* t    = (const float*)d_in[9];
    const float* gnw  = (const float*)d_in[10];
    const float* gnb  = (const float*)d_in[11];
    const float* gna  = (const float*)d_in[12];
    const float* linw = (const float*)d_in[13];
    const float* linb = (const float*)d_in[14];
    float* out = (float*)d_out;

    int n = in_sizes[0] / CC;   // 50000
    int E = in_sizes[1];        // 600000

    // x -> g_x
    k_copyin<<<2048, 256>>>(x, n * CC / 4);

    // CSR by dst (once per launch)
    k_zero_cursor<<<(n + 255) / 256, 256>>>(n);
    k_count<<<1024, 256>>>(dst, E);
    k_scan<<<1, 1024>>>(n);
    k_fill<<<1024, 256>>>(src, dst, E);

    int mBlocks = (n + 127) / 128;
    for (int l = 0; l < LL; l++) {
        k_zero_stats<<<1, 128>>>();
        k_gn_reduce<<<512, 128>>>(n);
        k_gn_apply<<<512, 128>>>(n, gnw + l * CC, gnb + l * CC, gna + l * CC);
        k_edge<<<(n + 7) / 8, 256>>>(n, t + l);
        dim3 g1(mBlocks, 2);
        k_gemm1<<<g1, 256>>>(n, W1 + (size_t)l * CC * HH, b1 + l * HH);
        dim3 g2(mBlocks, 1);
        k_gemm2<<<g2, 256>>>(n, W2 + (size_t)l * HH * CC, b2 + l * CC,
                             lnw + l * HH, lnb + l * HH);
    }
    k_final<<<(n + 7) / 8, 256>>>(n, linw, linb, out);
    (void)n_in; (void)out_size;
}

// round 3
// speedup vs baseline: 1.4071x; 1.4071x over previous
#include <cuda_runtime.h>
#include <cuda_bf16.h>
#include <cstdint>

#define CC 128
#define HH 256
#define LL 4
#define NMAX 50176
#define EMAX 602112

// ---------------- scratch (device globals; no allocation allowed) ------------
__device__ float  g_x [NMAX * CC];
__device__ float  g_h [NMAX * CC];
__device__ float  g_o [NMAX * CC];
__device__ float  g_h1[NMAX * HH];
__device__ int    g_rowptr[NMAX + 1];
__device__ int    g_cursor[NMAX];
__device__ int    g_col[EMAX];
__device__ int    g_part[64];
__device__ float  g_gnsum[CC];
__device__ float  g_gnsq [CC];
__device__ double g_lnsum;
__device__ double g_lnsq;
// bf16 hi/lo weight images, [n][k] row-major, per layer (32768 elems each)
__device__ __align__(16) __nv_bfloat16 g_B1h[LL * 32768];
__device__ __align__(16) __nv_bfloat16 g_B1l[LL * 32768];
__device__ __align__(16) __nv_bfloat16 g_B2h[LL * 32768];
__device__ __align__(16) __nv_bfloat16 g_B2l[LL * 32768];

// ---------------- mma.sync helpers (legal on plain sm_100) -------------------
__device__ __forceinline__ uint32_t smem_to_u32(const void* p) {
    uint32_t a;
    asm("{ .reg .u64 t; cvta.to.shared.u64 t, %1; cvt.u32.u64 %0, t; }" : "=r"(a) : "l"(p));
    return a;
}
__device__ __forceinline__ void ldsm4(uint32_t* r, uint32_t a) {
    asm volatile("ldmatrix.sync.aligned.m8n8.x4.shared.b16 {%0,%1,%2,%3}, [%4];"
                 : "=r"(r[0]), "=r"(r[1]), "=r"(r[2]), "=r"(r[3]) : "r"(a));
}
__device__ __forceinline__ void ldsm2(uint32_t* r, uint32_t a) {
    asm volatile("ldmatrix.sync.aligned.m8n8.x2.shared.b16 {%0,%1}, [%2];"
                 : "=r"(r[0]), "=r"(r[1]) : "r"(a));
}
__device__ __forceinline__ void mma_bf16(float* c, const uint32_t* a, const uint32_t* b) {
    asm volatile(
        "mma.sync.aligned.m16n8k16.row.col.f32.bf16.bf16.f32 "
        "{%0,%1,%2,%3}, {%4,%5,%6,%7}, {%8,%9}, {%0,%1,%2,%3};"
        : "+f"(c[0]), "+f"(c[1]), "+f"(c[2]), "+f"(c[3])
        : "r"(a[0]), "r"(a[1]), "r"(a[2]), "r"(a[3]), "r"(b[0]), "r"(b[1]));
}
__device__ __forceinline__ void bsplit(float v, __nv_bfloat16& h, __nv_bfloat16& l) {
    h = __float2bfloat16(v);
    l = __float2bfloat16(v - __bfloat162float(h));
}
__device__ __forceinline__ uint32_t pk(__nv_bfloat16 a, __nv_bfloat16 b) {
    __nv_bfloat162 t; t.x = a; t.y = b;
    return *reinterpret_cast<uint32_t*>(&t);
}

// smem tile pitch: 40 bf16 (80 B) -> ldmatrix rows hit distinct bank groups
#define PITCH 40

// ---------------- small utility kernels --------------------------------------
__global__ void k_copyin(const float* __restrict__ x, int n4)
{
    int i = blockIdx.x * blockDim.x + threadIdx.x;
    int stride = gridDim.x * blockDim.x;
    const float4* src = (const float4*)x;
    float4* dst = (float4*)g_x;
    for (; i < n4; i += stride) dst[i] = src[i];
}

__global__ void k_zero_cursor(int n)
{
    int i = blockIdx.x * blockDim.x + threadIdx.x;
    if (i < n) g_cursor[i] = 0;
}

__global__ void k_count(const int* __restrict__ dst, int E)
{
    int i = blockIdx.x * blockDim.x + threadIdx.x;
    int stride = gridDim.x * blockDim.x;
    for (; i < E; i += stride) atomicAdd(&g_cursor[dst[i]], 1);
}

__global__ void k_scan1(int n)
{
    __shared__ int sh[1024];
    int i = blockIdx.x * 1024 + threadIdx.x;
    int v = (i < n) ? g_cursor[i] : 0;
    sh[threadIdx.x] = v;
    __syncthreads();
    for (int off = 1; off < 1024; off <<= 1) {
        int tv = (threadIdx.x >= off) ? sh[threadIdx.x - off] : 0;
        __syncthreads();
        sh[threadIdx.x] += tv;
        __syncthreads();
    }
    if (i < n) g_rowptr[i] = sh[threadIdx.x] - v;
    if (threadIdx.x == 1023) g_part[blockIdx.x] = sh[1023];
}

__global__ void k_scan2(int nb, int n, int E)
{
    int tid = threadIdx.x;  // 64 threads
    int v = (tid < nb) ? g_part[tid] : 0;
    int x = v;
    for (int off = 1; off < 32; off <<= 1) {
        int y = __shfl_up_sync(0xFFFFFFFFu, x, off);
        if ((tid & 31) >= off) x += y;
    }
    __shared__ int c0;
    if (tid == 31) c0 = x;
    __syncthreads();
    if (tid >= 32) x += c0;
    if (tid < nb) g_part[tid] = x - v;
    if (tid == 0) g_rowptr[n] = E;
}

__global__ void k_scan3(int n)
{
    int i = blockIdx.x * blockDim.x + threadIdx.x;
    if (i < n) {
        int val = g_rowptr[i] + g_part[i >> 10];
        g_rowptr[i] = val;
        g_cursor[i] = val;
    }
}

__global__ void k_fill(const int* __restrict__ src, const int* __restrict__ dst, int E)
{
    int i = blockIdx.x * blockDim.x + threadIdx.x;
    int stride = gridDim.x * blockDim.x;
    for (; i < E; i += stride) {
        int p = atomicAdd(&g_cursor[dst[i]], 1);
        g_col[p] = src[i];
    }
}

__global__ void k_zero_stats()
{
    int i = threadIdx.x;
    g_gnsum[i] = 0.f;
    g_gnsq[i]  = 0.f;
    if (i == 0) { g_lnsum = 0.0; g_lnsq = 0.0; }
}

// weight pre-convert: bf16 hi/lo split, [n][k] row-major per layer
__global__ void k_wconv(const float* __restrict__ W1, const float* __restrict__ W2)
{
    int i = blockIdx.x * blockDim.x + threadIdx.x;
    if (i >= LL * 65536) return;
    int l = i >> 16;
    int r = i & 65535;
    __nv_bfloat16 h, lo;
    if (r < 32768) {                 // B1[n][k] = W1[l][k][n], n<256, k<128
        int n = r >> 7, k = r & 127;
        float v = W1[((size_t)l * CC + k) * HH + n];
        bsplit(v, h, lo);
        g_B1h[l * 32768 + n * 128 + k] = h;
        g_B1l[l * 32768 + n * 128 + k] = lo;
    } else {                          // B2[n][k] = W2[l][k][n], n<128, k<256
        r -= 32768;
        int n = r >> 8, k = r & 255;
        float v = W2[((size_t)l * HH + k) * CC + n];
        bsplit(v, h, lo);
        g_B2h[l * 32768 + n * 256 + k] = h;
        g_B2l[l * 32768 + n * 256 + k] = lo;
    }
}

// ---------------- GraphNorm ---------------------------------------------------
__global__ void k_gn_reduce(int n)
{
    int c = threadIdx.x;
    float s = 0.f, q = 0.f;
    for (int row = blockIdx.x; row < n; row += gridDim.x) {
        float v = g_x[(size_t)row * CC + c];
        s += v;
        q += v * v;
    }
    atomicAdd(&g_gnsum[c], s);
    atomicAdd(&g_gnsq[c],  q);
}

__global__ void k_gn_apply(int n, const float* __restrict__ gnw,
                           const float* __restrict__ gnb, const float* __restrict__ gna)
{
    int c = threadIdx.x;
    float invn  = 1.f / (float)n;
    float mean  = g_gnsum[c] * invn;
    float a     = gna[c];
    float var   = g_gnsq[c] * invn - (2.f * a - a * a) * mean * mean;
    float winv  = gnw[c] * rsqrtf(var + 1e-5f);
    float am    = a * mean;
    float b     = gnb[c];
    for (int row = blockIdx.x; row < n; row += gridDim.x) {
        float v = g_x[(size_t)row * CC + c];
        float y = winv * (v - am) + b;
        g_h[(size_t)row * CC + c] = fmaxf(y, 0.f);
    }
}

// -------- GENConv softmax aggregation: single pass (z bounded, no max) -------
__global__ void k_edge(int n, const float* __restrict__ t_ptr)
{
    int warp = (blockIdx.x * blockDim.x + threadIdx.x) >> 5;
    if (warp >= n) return;
    int lane = threadIdx.x & 31;
    float t = __ldg(t_ptr);
    int beg = g_rowptr[warp], end = g_rowptr[warp + 1];
    int co = lane * 4;

    float4 s1 = make_float4(0.f, 0.f, 0.f, 0.f);
    float4 s2 = make_float4(0.f, 0.f, 0.f, 0.f);
    for (int e = beg; e < end; e++) {
        int s = g_col[e];
        float4 v = *(const float4*)(g_h + (size_t)s * CC + co);
        float mX = v.x + 1e-7f;   // g_h >= 0 post-relu => relu(msg)=msg
        float mY = v.y + 1e-7f;
        float mZ = v.z + 1e-7f;
        float mW = v.w + 1e-7f;
        float eX = __expf(t * mX);
        float eY = __expf(t * mY);
        float eZ = __expf(t * mZ);
        float eW = __expf(t * mW);
        s1.x += eX; s1.y += eY; s1.z += eZ; s1.w += eW;
        s2.x += mX * eX; s2.y += mY * eY; s2.z += mZ * eZ; s2.w += mW * eW;
    }
    float4 hn = *(const float4*)(g_h + (size_t)warp * CC + co);
    float4 o;
    o.x = s2.x / (s1.x + 1e-16f) + hn.x;
    o.y = s2.y / (s1.y + 1e-16f) + hn.y;
    o.z = s2.z / (s1.z + 1e-16f) + hn.z;
    o.w = s2.w / (s1.w + 1e-16f) + hn.w;
    *(float4*)(g_o + (size_t)warp * CC + co) = o;
}

// ---------------- GEMM1 (mma.sync bf16-split): h1 = o @ W1 + b1 + LN stats ---
// block: 128 M x 128 N (grid.y picks N-half), K=128 in 4 chunks of 32
__global__ __launch_bounds__(256)
void k_gemm1_mma(int M, int layer, const float* __restrict__ b1l)
{
    __shared__ __align__(16) __nv_bfloat16 sm[4 * 128 * PITCH];
    __shared__ float rs[8], rq[8];
    const int AHI = 0, ALO = 128 * PITCH, BHI = 2 * 128 * PITCH, BLO = 3 * 128 * PITCH;

    int tid = threadIdx.x, lane = tid & 31, wid = tid >> 5;
    int wm = wid & 1, wn = wid >> 1;        // warp tile: 64 M x 32 N
    int rowBase = blockIdx.x * 128;
    int colBase = blockIdx.y * 128;
    const __nv_bfloat16* B1h = g_B1h + (size_t)layer * 32768;
    const __nv_bfloat16* B1l = g_B1l + (size_t)layer * 32768;
    uint32_t sbase = smem_to_u32(sm);

    float c[4][4][4];
#pragma unroll
    for (int mt = 0; mt < 4; mt++)
#pragma unroll
        for (int nt = 0; nt < 4; nt++)
#pragma unroll
            for (int q = 0; q < 4; q++) c[mt][nt][q] = 0.f;

    for (int kc = 0; kc < CC; kc += 32) {
        // stage A (fp32 -> bf16 hi/lo), 128 rows x 32 k
#pragma unroll
        for (int it = 0; it < 4; it++) {
            int i = tid + it * 256;               // 1024 float4 slots
            int row = i >> 3, q = i & 7;
            float4 v = make_float4(0.f, 0.f, 0.f, 0.f);
            if (rowBase + row < M)
                v = *(const float4*)(g_o + (size_t)(rowBase + row) * CC + kc + q * 4);
            __nv_bfloat16 h0, h1, h2, h3, l0, l1, l2, l3;
            bsplit(v.x, h0, l0); bsplit(v.y, h1, l1);
            bsplit(v.z, h2, l2); bsplit(v.w, h3, l3);
            int off = row * PITCH + q * 4;
            *(uint2*)(sm + AHI + off) = make_uint2(pk(h0, h1), pk(h2, h3));
            *(uint2*)(sm + ALO + off) = make_uint2(pk(l0, l1), pk(l2, l3));
        }
        // stage B (pre-split bf16), 128 n-rows x 32 k
#pragma unroll
        for (int it = 0; it < 2; it++) {
            int i = tid + it * 256;               // 512 uint4 slots
            int row = i >> 2, q = i & 3;
            size_t goff = (size_t)(colBase + row) * CC + kc + q * 8;
            int off = row * PITCH + q * 8;
            *(uint4*)(sm + BHI + off) = *(const uint4*)(B1h + goff);
            *(uint4*)(sm + BLO + off) = *(const uint4*)(B1l + goff);
        }
        __syncthreads();

#pragma unroll
        for (int ks = 0; ks < 2; ks++) {
            uint32_t bh[4][2], bl[4][2];
#pragma unroll
            for (int nt = 0; nt < 4; nt++) {
                uint32_t ab = sbase + 2 * (BHI + (wn * 32 + nt * 8 + (lane & 7)) * PITCH
                                           + ks * 16 + ((lane >> 3) & 1) * 8);
                ldsm2(bh[nt], ab);
                ldsm2(bl[nt], ab + 2 * (BLO - BHI));
            }
#pragma unroll
            for (int mt = 0; mt < 4; mt++) {
                uint32_t aa = sbase + 2 * (AHI + (wm * 64 + mt * 16 + (lane & 15)) * PITCH
                                           + ks * 16 + (lane >> 4) * 8);
                uint32_t ah[4], al[4];
                ldsm4(ah, aa);
                ldsm4(al, aa + 2 * (ALO - AHI));
#pragma unroll
                for (int nt = 0; nt < 4; nt++) {
                    mma_bf16(c[mt][nt], ah, bh[nt]);
                    mma_bf16(c[mt][nt], ah, bl[nt]);
                    mma_bf16(c[mt][nt], al, bh[nt]);
                }
            }
        }
        __syncthreads();
    }

    // epilogue: bias add, store h1, LN stats
    float lsum = 0.f, lsq = 0.f;
    int mrow0 = rowBase + wm * 64;
    int col0  = colBase + wn * 32;
#pragma unroll
    for (int mt = 0; mt < 4; mt++) {
#pragma unroll
        for (int nt = 0; nt < 4; nt++) {
            int gm = mrow0 + mt * 16 + (lane >> 2);
            int gn = col0 + nt * 8 + (lane & 3) * 2;
            float b0 = b1l[gn], b1_ = b1l[gn + 1];
            if (gm < M) {
                float v0 = c[mt][nt][0] + b0;
                float v1 = c[mt][nt][1] + b1_;
                *(float2*)(g_h1 + (size_t)gm * HH + gn) = make_float2(v0, v1);
                lsum += v0 + v1;
                lsq  += v0 * v0 + v1 * v1;
            }
            if (gm + 8 < M) {
                float v2 = c[mt][nt][2] + b0;
                float v3 = c[mt][nt][3] + b1_;
                *(float2*)(g_h1 + (size_t)(gm + 8) * HH + gn) = make_float2(v2, v3);
                lsum += v2 + v3;
                lsq  += v2 * v2 + v3 * v3;
            }
        }
    }
    for (int off = 16; off; off >>= 1) {
        lsum += __shfl_down_sync(0xFFFFFFFFu, lsum, off);
        lsq  += __shfl_down_sync(0xFFFFFFFFu, lsq,  off);
    }
    if (lane == 0) { rs[wid] = lsum; rq[wid] = lsq; }
    __syncthreads();
    if (tid == 0) {
        float s = 0.f, q = 0.f;
        for (int w = 0; w < 8; w++) { s += rs[w]; q += rq[w]; }
        atomicAdd(&g_lnsum, (double)s);
        atomicAdd(&g_lnsq,  (double)q);
    }
}

// ------ GEMM2 (mma.sync): x += relu(LN(h1)*lnw+lnb) @ W2 + b2 ----------------
// block: 128 M x 128 N (full), K=256 in 8 chunks of 32
__global__ __launch_bounds__(256)
void k_gemm2_mma(int M, int layer, const float* __restrict__ b2l,
                 const float* __restrict__ lnw, const float* __restrict__ lnb)
{
    __shared__ __align__(16) __nv_bfloat16 sm[4 * 128 * PITCH];
    const int AHI = 0, ALO = 128 * PITCH, BHI = 2 * 128 * PITCH, BLO = 3 * 128 * PITCH;

    int tid = threadIdx.x, lane = tid & 31, wid = tid >> 5;
    int wm = wid & 1, wn = wid >> 1;
    int rowBase = blockIdx.x * 128;
    const __nv_bfloat16* B2h = g_B2h + (size_t)layer * 32768;
    const __nv_bfloat16* B2l = g_B2l + (size_t)layer * 32768;
    uint32_t sbase = smem_to_u32(sm);

    double cnt = (double)M * (double)HH;
    double dm  = g_lnsum / cnt;
    double dv  = g_lnsq / cnt - dm * dm;
    float mean = (float)dm;
    float inv  = 1.f / (sqrtf(fmaxf((float)dv, 0.f)) + 1e-5f);

    float c[4][4][4];
#pragma unroll
    for (int mt = 0; mt < 4; mt++)
#pragma unroll
        for (int nt = 0; nt < 4; nt++)
#pragma unroll
            for (int q = 0; q < 4; q++) c[mt][nt][q] = 0.f;

    for (int kc = 0; kc < HH; kc += 32) {
        // stage A: relu(LN(h1)) -> bf16 hi/lo
#pragma unroll
        for (int it = 0; it < 4; it++) {
            int i = tid + it * 256;
            int row = i >> 3, q = i & 7;
            int gk = kc + q * 4;
            float4 v = make_float4(0.f, 0.f, 0.f, 0.f);
            if (rowBase + row < M)
                v = *(const float4*)(g_h1 + (size_t)(rowBase + row) * HH + gk);
            float4 w4 = *(const float4*)(lnw + gk);
            float4 b4 = *(const float4*)(lnb + gk);
            v.x = fmaxf((v.x - mean) * inv * w4.x + b4.x, 0.f);
            v.y = fmaxf((v.y - mean) * inv * w4.y + b4.y, 0.f);
            v.z = fmaxf((v.z - mean) * inv * w4.z + b4.z, 0.f);
            v.w = fmaxf((v.w - mean) * inv * w4.w + b4.w, 0.f);
            __nv_bfloat16 h0, h1, h2, h3, l0, l1, l2, l3;
            bsplit(v.x, h0, l0); bsplit(v.y, h1, l1);
            bsplit(v.z, h2, l2); bsplit(v.w, h3, l3);
            int off = row * PITCH + q * 4;
            *(uint2*)(sm + AHI + off) = make_uint2(pk(h0, h1), pk(h2, h3));
            *(uint2*)(sm + ALO + off) = make_uint2(pk(l0, l1), pk(l2, l3));
        }
#pragma unroll
        for (int it = 0; it < 2; it++) {
            int i = tid + it * 256;
            int row = i >> 2, q = i & 3;
            size_t goff = (size_t)row * HH + kc + q * 8;
            int off = row * PITCH + q * 8;
            *(uint4*)(sm + BHI + off) = *(const uint4*)(B2h + goff);
            *(uint4*)(sm + BLO + off) = *(const uint4*)(B2l + goff);
        }
        __syncthreads();

#pragma unroll
        for (int ks = 0; ks < 2; ks++) {
            uint32_t bh[4][2], bl[4][2];
#pragma unroll
            for (int nt = 0; nt < 4; nt++) {
                uint32_t ab = sbase + 2 * (BHI + (wn * 32 + nt * 8 + (lane & 7)) * PITCH
                                           + ks * 16 + ((lane >> 3) & 1) * 8);
                ldsm2(bh[nt], ab);
                ldsm2(bl[nt], ab + 2 * (BLO - BHI));
            }
#pragma unroll
            for (int mt = 0; mt < 4; mt++) {
                uint32_t aa = sbase + 2 * (AHI + (wm * 64 + mt * 16 + (lane & 15)) * PITCH
                                           + ks * 16 + (lane >> 4) * 8);
                uint32_t ah[4], al[4];
                ldsm4(ah, aa);
                ldsm4(al, aa + 2 * (ALO - AHI));
#pragma unroll
                for (int nt = 0; nt < 4; nt++) {
                    mma_bf16(c[mt][nt], ah, bh[nt]);
                    mma_bf16(c[mt][nt], ah, bl[nt]);
                    mma_bf16(c[mt][nt], al, bh[nt]);
                }
            }
        }
        __syncthreads();
    }

    // epilogue: residual add into g_x
    int mrow0 = rowBase + wm * 64;
    int col0  = wn * 32;
#pragma unroll
    for (int mt = 0; mt < 4; mt++) {
#pragma unroll
        for (int nt = 0; nt < 4; nt++) {
            int gm = mrow0 + mt * 16 + (lane >> 2);
            int gn = col0 + nt * 8 + (lane & 3) * 2;
            float b0 = b2l[gn], b1_ = b2l[gn + 1];
            if (gm < M) {
                float2 old = *(float2*)(g_x + (size_t)gm * CC + gn);
                *(float2*)(g_x + (size_t)gm * CC + gn) =
                    make_float2(old.x + c[mt][nt][0] + b0, old.y + c[mt][nt][1] + b1_);
            }
            if (gm + 8 < M) {
                float2 old = *(float2*)(g_x + (size_t)(gm + 8) * CC + gn);
                *(float2*)(g_x + (size_t)(gm + 8) * CC + gn) =
                    make_float2(old.x + c[mt][nt][2] + b0, old.y + c[mt][nt][3] + b1_);
            }
        }
    }
}

// ---------------- final projection x @ lin_w + lin_b -------------------------
__global__ void k_final(int n, const float* __restrict__ linw,
                        const float* __restrict__ linb, float* __restrict__ out)
{
    int row = (blockIdx.x * blockDim.x + threadIdx.x) >> 5;
    if (row >= n) return;
    int lane = threadIdx.x & 31;
    float4 x4 = *(const float4*)(g_x + (size_t)row * CC + lane * 4);
    float4 w4 = *(const float4*)(linw + lane * 4);
    float s = x4.x * w4.x + x4.y * w4.y + x4.z * w4.z + x4.w * w4.w;
    for (int off = 16; off; off >>= 1) s += __shfl_down_sync(0xFFFFFFFFu, s, off);
    if (lane == 0) out[row] = s + __ldg(linb);
}

// ---------------- launch ------------------------------------------------------
extern "C" void kernel_launch(void* const* d_in, const int* in_sizes, int n_in,
                              void* d_out, int out_size)
{
    const float* x    = (const float*)d_in[0];
    const int*   src  = (const int*)  d_in[1];
    const int*   dst  = (const int*)  d_in[2];
    const float* W1   = (const float*)d_in[3];
    const float* b1   = (const float*)d_in[4];
    const float* lnw  = (const float*)d_in[5];
    const float* lnb  = (const float*)d_in[6];
    const float* W2   = (const float*)d_in[7];
    const float* b2   = (const float*)d_in[8];
    const float* t    = (const float*)d_in[9];
    const float* gnw  = (const float*)d_in[10];
    const float* gnb  = (const float*)d_in[11];
    const float* gna  = (const float*)d_in[12];
    const float* linw = (const float*)d_in[13];
    const float* linb = (const float*)d_in[14];
    float* out = (float*)d_out;

    int n = in_sizes[0] / CC;   // 50000
    int E = in_sizes[1];        // 600000

    k_copyin<<<2048, 256>>>(x, n * CC / 4);
    k_wconv<<<1024, 256>>>(W1, W2);

    // CSR by dst
    int nb = (n + 1023) / 1024;
    k_zero_cursor<<<(n + 255) / 256, 256>>>(n);
    k_count<<<1024, 256>>>(dst, E);
    k_scan1<<<nb, 1024>>>(n);
    k_scan2<<<1, 64>>>(nb, n, E);
    k_scan3<<<(n + 255) / 256, 256>>>(n);
    k_fill<<<1024, 256>>>(src, dst, E);

    int mBlocks = (n + 127) / 128;
    for (int l = 0; l < LL; l++) {
        k_zero_stats<<<1, 128>>>();
        k_gn_reduce<<<512, 128>>>(n);
        k_gn_apply<<<512, 128>>>(n, gnw + l * CC, gnb + l * CC, gna + l * CC);
        k_edge<<<(n + 7) / 8, 256>>>(n, t + l);
        dim3 g1(mBlocks, 2);
        k_gemm1_mma<<<g1, 256>>>(n, l, b1 + l * HH);
        k_gemm2_mma<<<mBlocks, 256>>>(n, l, b2 + l * CC, lnw + l * HH, lnb + l * HH);
    }
    k_final<<<(n + 7) / 8, 256>>>(n, linw, linb, out);
    (void)n_in; (void)out_size;
}